// round 14
// baseline (speedup 1.0000x reference)
#include <cuda_runtime.h>
#include <cuda_bf16.h>
#include <math.h>

// Problem constants
#define PC_SRC   64000
#define REF_SRC  80000
#define N_PC     8000
#define N_REF    10000

#define GRID     592           // 4 blocks/SM x 148 SMs, all co-resident
#define THREADS  256
#define NPT      4             // points per thread
#define PTS      (THREADS * NPT)   // 1024 points per chunk

// Direction A: P = pc (8000), R = ref (10000): 8 x-chunks * 74 y-tiles = 592
#define XC_A     8
#define YT_A     74
#define TILE     136
#define HTILE    68
// Direction B: P = ref (10000), R = pc (8000): 10 x-chunks * 59 y-tiles = 590
#define XC_B     10
#define NCHUNK_B 590

#define INF_BITS 0x7F800000u
#define FINF __int_as_float(0x7F800000)

// Device-global scratch (allocation forbidden).
// g_max holds (INF_BITS - d2_bits); 0 == identity == "+inf distance".
// .bss zero-init makes the first call correct; finish resets slots to 0
// after consuming, so every graph replay starts clean.
__device__ unsigned g_max1[N_PC];
__device__ unsigned g_max2[N_REF];
__device__ double   g_sum;
__device__ unsigned g_bar2, g_done;

typedef unsigned long long ull;

union U64 { ull u; float2 f; };

static __device__ __forceinline__ ull pack2(float lo, float hi) {
    U64 v; v.f = make_float2(lo, hi); return v.u;
}
static __device__ __forceinline__ ull fma2(ull a, ull b, ull c) {
    ull d; asm("fma.rn.f32x2 %0, %1, %2, %3;" : "=l"(d) : "l"(a), "l"(b), "l"(c));
    return d;
}

// linspace(0, nsrc-1, nsub) index, faithful fp32 torch/jax semantics
static __device__ __forceinline__ int lin_idx(int i, int nsrc, int nsub) {
    float delta = (float)(nsrc - 1) / (float)(nsub - 1);
    int idx = (int)((float)i * delta);          // fp32 mul + trunc
    return (idx > nsrc - 1) ? (nsrc - 1) : idx;
}

// Stage one packed tile straight from raw source (gather + preprocess).
static __device__ __forceinline__ void stage_tile(
    const float* __restrict__ src, int nsrc, int nsub, int rbase,
    ulonglong2* __restrict__ sXY, ull* __restrict__ sZ, int lane)
{
    float x0 = 0.f, y0 = 0.f, z0 = 1e30f;
    float x1 = 0.f, y1 = 0.f, z1 = 1e30f;
    int r0 = rbase + 2 * lane, r1 = r0 + 1;
    if (r0 < nsub) {
        int idx = lin_idx(r0, nsrc, nsub);
        float rx = src[2 * idx] - 0.5f, ry = src[2 * idx + 1] - 0.5f;
        x0 = -2.f * rx; y0 = -2.f * ry; z0 = fmaf(rx, rx, ry * ry);
    }
    if (r1 < nsub) {
        int idx = lin_idx(r1, nsrc, nsub);
        float rx = src[2 * idx] - 0.5f, ry = src[2 * idx + 1] - 0.5f;
        x1 = -2.f * rx; y1 = -2.f * ry; z1 = fmaf(rx, rx, ry * ry);
    }
    sXY[lane] = make_ulonglong2(pack2(x0, x1), pack2(y0, y1));
    sZ[lane]  = pack2(z0, z1);
}

// Per-chunk compute: NPT raw-gathered points/thread vs one staged tile.
static __device__ __forceinline__ void run_chunk(
    const float* __restrict__ Psrc, int nsrcP, unsigned* __restrict__ gmax,
    const ulonglong2* __restrict__ sXY, const ull* __restrict__ sZ,
    int np, int xc, int tid)
{
    const int ib = xc * PTS + tid;
    ull px2[NPT], py2[NPT];
    float pp[NPT];
#pragma unroll
    for (int k = 0; k < NPT; k++) {
        int i = ib + k * THREADS;
        int idx = lin_idx((i < np) ? i : (np - 1), nsrcP, np);
        float x = Psrc[2 * idx] - 0.5f, y = Psrc[2 * idx + 1] - 0.5f;
        // packed as (+x/... ) NOTE: tile holds -2r, so use p directly scaled:
        // t = (-2rx)*px + (-2ry)*py + |r|^2 ; we fold the 1x scale here.
        px2[k] = pack2(x, x);
        py2[k] = pack2(y, y);
        pp[k]  = fmaf(x, x, y * y);
    }

    float mA[NPT], mB[NPT];
#pragma unroll
    for (int k = 0; k < NPT; k++) { mA[k] = FINF; mB[k] = FINF; }

#pragma unroll 4
    for (int j = 0; j < HTILE; j++) {
        ulonglong2 xy = sXY[j];     // (rx2, ry2) packed, already scaled by -2
        ull rz2 = sZ[j];
#pragma unroll
        for (int k = 0; k < NPT; k++) {
            U64 t; t.u = fma2(px2[k], xy.x, fma2(py2[k], xy.y, rz2));
            mA[k] = fminf(mA[k], t.f.x);
            mB[k] = fminf(mB[k], t.f.y);
        }
    }

#pragma unroll
    for (int k = 0; k < NPT; k++) {
        int i = ib + k * THREADS;
        if (i < np) {
            float v = fmaxf(pp[k] + fminf(mA[k], mB[k]), 0.0f);
            // store INF_BITS - bits via RED.MAX: 0 is the identity -> no init pass
            atomicMax(&gmax[i], INF_BITS - __float_as_uint(v));
        }
    }
}

__global__ void __launch_bounds__(THREADS, 4) chamfer_kernel(
    const float* __restrict__ pc_src, const float* __restrict__ ref_src,
    float* __restrict__ out)
{
    const int tid = threadIdx.x;
    const int bid = blockIdx.x;
    const int gtid = bid * THREADS + tid;
    const bool leader = (tid == 0);

    __shared__ ulonglong2 sXY_A[HTILE], sXY_B[HTILE];
    __shared__ ull        sZ_A[HTILE],  sZ_B[HTILE];
    __shared__ double warp_s[8];

    // ---- Phase 1 (immediately): one A-chunk + one B-chunk per block
    const int xcA = bid % XC_A, ycA = bid / XC_A;      // A chunk = bid (0..591)
    const bool hasB = (bid < NCHUNK_B);
    const int xcB = bid % XC_B, ycB = bid / XC_B;      // B chunk = bid (0..589)

    // stage both tiles concurrently with different warps, one barrier total
    if (tid < HTILE)
        stage_tile(ref_src, REF_SRC, N_REF, ycA * TILE, sXY_A, sZ_A, tid);
    else if (tid >= 128 && tid < 128 + HTILE && hasB)
        stage_tile(pc_src, PC_SRC, N_PC, ycB * TILE, sXY_B, sZ_B, tid - 128);
    __syncthreads();

    run_chunk(pc_src, PC_SRC, g_max1, sXY_A, sZ_A, N_PC, xcA, tid);
    if (hasB)
        run_chunk(ref_src, REF_SRC, g_max2, sXY_B, sZ_B, N_REF, xcB, tid);

    // ---- barrier (all RED.MAXs visible)
    __threadfence();
    __syncthreads();
    if (leader) {
        atomicAdd(&g_bar2, 1u);
        while (*((volatile unsigned*)&g_bar2) < GRID) __nanosleep(32);
    }
    __syncthreads();

    // ---- Phase 2: finish (one load + sqrt per point; reset slot for replay)
    double local = 0.0;
    if (gtid < N_PC + N_REF) {
        if (gtid < N_PC) {
            unsigned s = __ldcg(&g_max1[gtid]);
            g_max1[gtid] = 0u;                       // identity for next replay
            local = (double)sqrtf(__uint_as_float(INF_BITS - s))
                    * (0.5 / (double)N_PC);
        } else {
            int i = gtid - N_PC;
            unsigned s = __ldcg(&g_max2[i]);
            g_max2[i] = 0u;
            local = (double)sqrtf(__uint_as_float(INF_BITS - s))
                    * (0.5 / (double)N_REF);
        }
    }
    for (int off = 16; off > 0; off >>= 1)
        local += __shfl_down_sync(0xFFFFFFFFu, local, off);
    const int wid = tid >> 5, lid = tid & 31;
    if (lid == 0) warp_s[wid] = local;
    __syncthreads();
    if (wid == 0) {
        local = (lid < 8) ? warp_s[lid] : 0.0;
        for (int off = 4; off > 0; off >>= 1)
            local += __shfl_down_sync(0xFFFFFFFFu, local, off);
        if (lid == 0) {
            if (local != 0.0) atomicAdd(&g_sum, local);
            __threadfence();
            unsigned t = atomicAdd(&g_done, 1u);
            if (t == GRID - 1) {
                // last block: publish + reset remaining state for next replay
                double s = *((volatile double*)&g_sum);
                out[0] = (float)s;
                g_sum = 0.0;
                g_bar2 = 0u; g_done = 0u;
                __threadfence();
            }
        }
    }
}

extern "C" void kernel_launch(void* const* d_in, const int* in_sizes, int n_in,
                              void* d_out, int out_size)
{
    const float* pc_src  = (const float*)d_in[0];  // (1000,64,2) fp32
    const float* ref_src = (const float*)d_in[1];  // (80000,2)  fp32
    float* out = (float*)d_out;

    chamfer_kernel<<<GRID, THREADS>>>(pc_src, ref_src, out);
}